// round 5
// baseline (speedup 1.0000x reference)
#include <cuda_runtime.h>
#include <cuda_bf16.h>
#include <cstdint>

#define B_ 4096
#define N_ 32768
#define D_ 1024
#define BM 128
#define BN 128
#define NSTAGE 3
#define KSLABS 8                // D_ int8 bytes / 128
#define SLAB 16384              // 128 rows * 128B (one operand, one k-slab)
#define STAGE_BYTES (2*SLAB)    // A + B
#define NBLK (N_/BN)            // 256 n-blocks per row
#define NSUB (N_/16)            // 2048 16-key sub-blocks per row
#define EPSTR 132
#define MARGIN 0.004f

// ------------------------- scratch (no allocations allowed) -------------------------
__device__ float         g_qn[(size_t)B_*D_];     // normalized Q fp32 (refinement)
__device__ unsigned char g_qsw[(size_t)B_*D_];    // Q int8, slab-contiguous SW128 layout
__device__ unsigned char g_ksw[(size_t)N_*D_];    // K int8, slab-contiguous SW128 layout
__device__ float         g_qs[B_];                // q dequant scale
__device__ float         g_ks[N_];                // k dequant scale
__device__ float         g_kinv[N_];              // 1/||k||
__device__ float2        g_part[(size_t)B_*NBLK]; // per (row, nblock): (sum, sumsq)
__device__ float         g_topv[(size_t)B_*NSUB]; // per (row, subblock): approx max sim
__device__ float         g_var[B_];

// ------------------------- helpers -------------------------
__device__ __forceinline__ uint32_t cvta_s(const void* p) {
    return (uint32_t)__cvta_generic_to_shared(p);
}
__device__ __forceinline__ void cp_async16(uint32_t dst, const void* src) {
    asm volatile("cp.async.cg.shared.global [%0], [%1], 16;\n" :: "r"(dst), "l"(src));
}
__device__ __forceinline__ void cp_commit() {
    asm volatile("cp.async.commit_group;\n" ::: "memory");
}
template <int NN> __device__ __forceinline__ void cp_wait() {
    asm volatile("cp.async.wait_group %0;\n" :: "n"(NN) : "memory");
}
__device__ __forceinline__ void ldsm4(uint32_t& r0, uint32_t& r1, uint32_t& r2, uint32_t& r3, uint32_t a) {
    asm volatile("ldmatrix.sync.aligned.m8n8.x4.shared.b16 {%0,%1,%2,%3},[%4];\n"
        : "=r"(r0), "=r"(r1), "=r"(r2), "=r"(r3) : "r"(a));
}
__device__ __forceinline__ void imma16832(int* c, const uint32_t* a, const uint32_t* b) {
    asm volatile("mma.sync.aligned.m16n8k32.row.col.s32.s8.s8.s32 "
        "{%0,%1,%2,%3},{%4,%5,%6,%7},{%8,%9},{%0,%1,%2,%3};\n"
        : "+r"(c[0]), "+r"(c[1]), "+r"(c[2]), "+r"(c[3])
        : "r"(a[0]), "r"(a[1]), "r"(a[2]), "r"(a[3]), "r"(b[0]), "r"(b[1]));
}
// byte offset of (row, colByte) inside a 128x128B SW128 tile (XOR on bits 4-6)
__device__ __forceinline__ uint32_t swz(uint32_t r, uint32_t cByte) {
    return r * 128u + (cByte ^ ((r & 7u) << 4));
}

// ------------------------- normalize + int8 quantize (SW128 slab layout) -------------------------
__global__ void norm_rows_q(const float* __restrict__ x) {
    int row = blockIdx.x, tid = threadIdx.x;
    const float4* xp = (const float4*)(x + (size_t)row * D_);
    float4 a = xp[tid];
    float ss = a.x*a.x + a.y*a.y + a.z*a.z + a.w*a.w;
    float ma = fmaxf(fmaxf(fabsf(a.x), fabsf(a.y)), fmaxf(fabsf(a.z), fabsf(a.w)));
    __shared__ float sh[256], shm[256];
    sh[tid] = ss; shm[tid] = ma; __syncthreads();
    for (int s = 128; s > 0; s >>= 1) {
        if (tid < s) { sh[tid] += sh[tid+s]; shm[tid] = fmaxf(shm[tid], shm[tid+s]); }
        __syncthreads();
    }
    float inv = 1.0f / fmaxf(sqrtf(sh[0]), 1e-12f);
    float sq = fmaxf(shm[0] * inv, 1e-20f) * (1.0f / 127.0f);
    if (tid == 0) g_qs[row] = sq;
    float4 o; o.x = a.x*inv; o.y = a.y*inv; o.z = a.z*inv; o.w = a.w*inv;
    ((float4*)(g_qn + (size_t)row * D_))[tid] = o;
    float qs = 1.0f / sq;
    int i0 = __float2int_rn(o.x*qs), i1 = __float2int_rn(o.y*qs);
    int i2 = __float2int_rn(o.z*qs), i3 = __float2int_rn(o.w*qs);
    uint32_t pk = (uint32_t)(i0 & 255) | ((uint32_t)(i1 & 255) << 8)
                | ((uint32_t)(i2 & 255) << 16) | ((uint32_t)(i3 & 255) << 24);
    int mt = row >> 7, r_in = row & 127;
    int kslab = tid >> 5;                          // 32 threads (128 bytes) per k-slab
    uint32_t b = (uint32_t)((tid & 31) * 4);
    uint32_t off = (uint32_t)r_in * 128u + (((b & ~15u) ^ ((uint32_t)(r_in & 7) << 4)) | (b & 15u));
    *(uint32_t*)(g_qsw + (size_t)(mt * KSLABS + kslab) * SLAB + off) = pk;
}

__global__ void norm_rows_k(const float* __restrict__ x) {
    int row = blockIdx.x, tid = threadIdx.x;
    const float4* xp = (const float4*)(x + (size_t)row * D_);
    float4 a = xp[tid];
    float ss = a.x*a.x + a.y*a.y + a.z*a.z + a.w*a.w;
    float ma = fmaxf(fmaxf(fabsf(a.x), fabsf(a.y)), fmaxf(fabsf(a.z), fabsf(a.w)));
    __shared__ float sh[256], shm[256];
    sh[tid] = ss; shm[tid] = ma; __syncthreads();
    for (int s = 128; s > 0; s >>= 1) {
        if (tid < s) { sh[tid] += sh[tid+s]; shm[tid] = fmaxf(shm[tid], shm[tid+s]); }
        __syncthreads();
    }
    float inv = 1.0f / fmaxf(sqrtf(sh[0]), 1e-12f);
    float sk = fmaxf(shm[0] * inv, 1e-20f) * (1.0f / 127.0f);
    if (tid == 0) { g_kinv[row] = inv; g_ks[row] = sk; }
    float4 o; o.x = a.x*inv; o.y = a.y*inv; o.z = a.z*inv; o.w = a.w*inv;
    float qs = 1.0f / sk;
    int i0 = __float2int_rn(o.x*qs), i1 = __float2int_rn(o.y*qs);
    int i2 = __float2int_rn(o.z*qs), i3 = __float2int_rn(o.w*qs);
    uint32_t pk = (uint32_t)(i0 & 255) | ((uint32_t)(i1 & 255) << 8)
                | ((uint32_t)(i2 & 255) << 16) | ((uint32_t)(i3 & 255) << 24);
    int nt = row >> 7, r_in = row & 127;
    int kslab = tid >> 5;
    uint32_t b = (uint32_t)((tid & 31) * 4);
    uint32_t off = (uint32_t)r_in * 128u + (((b & ~15u) ^ ((uint32_t)(r_in & 7) << 4)) | (b & 15u));
    *(uint32_t*)(g_ksw + (size_t)(nt * KSLABS + kslab) * SLAB + off) = pk;
}

// ------------------------- GEMM: int8 mma.sync + cp.async 3-stage pipeline -------------------------
__global__ __launch_bounds__(256, 2) void sim_gemm() {
    extern __shared__ __align__(16) unsigned char smraw[];   // NSTAGE * 32KB
    float* ep = (float*)smraw;
    __shared__ float sks_s[BN];

    const int tid = threadIdx.x;
    const int lane = tid & 31, warp = tid >> 5;
    const int wm = (warp >> 2) * 64;
    const int wn = (warp & 3) * 32;
    const int mt = blockIdx.x;
    const int nt = blockIdx.y;
    const int m0 = mt * BM, n0 = nt * BN;

    if (tid < BN) sks_s[tid] = g_ks[n0 + tid];

    const unsigned char* qbase = g_qsw + (size_t)mt * KSLABS * SLAB;
    const unsigned char* kbase = g_ksw + (size_t)nt * KSLABS * SLAB;
    const uint32_t sbase = cvta_s(smraw);

    int acc[4][4][4];
    #pragma unroll
    for (int i = 0; i < 4; i++)
        #pragma unroll
        for (int j = 0; j < 4; j++)
            #pragma unroll
            for (int k = 0; k < 4; k++) acc[i][j][k] = 0;

    // prologue: slabs 0,1 into stages 0,1
    #pragma unroll
    for (int s = 0; s < NSTAGE - 1; ++s) {
        uint32_t st = sbase + s * STAGE_BYTES;
        #pragma unroll
        for (int i = 0; i < 4; ++i) {
            uint32_t o = (uint32_t)(i * 4096 + tid * 16);
            cp_async16(st + o,        qbase + (size_t)s * SLAB + o);
            cp_async16(st + SLAB + o, kbase + (size_t)s * SLAB + o);
        }
        cp_commit();
    }

    const uint32_t rsel = lane & 15;
    const uint32_t cbase = (uint32_t)((lane >> 4) << 4);   // 0 or 16 bytes

    #pragma unroll 1
    for (int t = 0; t < KSLABS; ++t) {
        cp_wait<1>();
        __syncthreads();
        if (t + NSTAGE - 1 < KSLABS) {
            int s2 = (t + NSTAGE - 1) % NSTAGE;
            uint32_t st = sbase + s2 * STAGE_BYTES;
            #pragma unroll
            for (int i = 0; i < 4; ++i) {
                uint32_t o = (uint32_t)(i * 4096 + tid * 16);
                cp_async16(st + o,        qbase + (size_t)(t + NSTAGE - 1) * SLAB + o);
                cp_async16(st + SLAB + o, kbase + (size_t)(t + NSTAGE - 1) * SLAB + o);
            }
        }
        cp_commit();

        uint32_t sA = sbase + (t % NSTAGE) * STAGE_BYTES;
        uint32_t sB = sA + SLAB;
        #pragma unroll
        for (int kk = 0; kk < 4; ++kk) {               // 4 x k=32B per 128B slab
            uint32_t cByte = (uint32_t)(kk * 32) + cbase;
            uint32_t af[4][4], bf[4][2];
            #pragma unroll
            for (int mi = 0; mi < 4; ++mi)
                ldsm4(af[mi][0], af[mi][1], af[mi][2], af[mi][3],
                      sA + swz(wm + mi * 16 + rsel, cByte));
            #pragma unroll
            for (int nh = 0; nh < 2; ++nh) {
                uint32_t r0, r1, r2, r3;
                ldsm4(r0, r1, r2, r3, sB + swz(wn + nh * 16 + rsel, cByte));
                bf[nh*2+0][0] = r0; bf[nh*2+0][1] = r2;
                bf[nh*2+1][0] = r1; bf[nh*2+1][1] = r3;
            }
            #pragma unroll
            for (int mi = 0; mi < 4; ++mi)
                #pragma unroll
                for (int ni = 0; ni < 4; ++ni)
                    imma16832(acc[mi][ni], af[mi], bf[ni]);
        }
    }
    __syncthreads();   // compute done; smem becomes epilogue buffer

    // epilogue: two phases of 64 rows; writer dequants by sk[col], reader by sq[row]
    #pragma unroll 1
    for (int ph = 0; ph < 2; ++ph) {
        if ((warp >> 2) == ph) {
            #pragma unroll
            for (int mi = 0; mi < 4; ++mi)
                #pragma unroll
                for (int ni = 0; ni < 4; ++ni) {
                    int r = mi * 16 + (lane >> 2);
                    int c = wn + ni * 8 + ((lane & 3) << 1);
                    float k0 = sks_s[c], k1 = sks_s[c + 1];
                    ep[r * EPSTR + c]           = (float)acc[mi][ni][0] * k0;
                    ep[r * EPSTR + c + 1]       = (float)acc[mi][ni][1] * k1;
                    ep[(r + 8) * EPSTR + c]     = (float)acc[mi][ni][2] * k0;
                    ep[(r + 8) * EPSTR + c + 1] = (float)acc[mi][ni][3] * k1;
                }
        }
        __syncthreads();
        {
            int r = tid >> 2, tq = tid & 3;        // 4 threads per row, 32 cols each
            const float* rowp = ep + r * EPSTR + tq * 32;
            int grow = m0 + ph * 64 + r;
            float sqv = g_qs[grow];
            float s = 0.f, q2 = 0.f;
            #pragma unroll
            for (int h = 0; h < 2; ++h) {          // two 16-key sub-blocks
                float mv = -1e30f;
                #pragma unroll
                for (int c = 0; c < 16; ++c) {
                    float v = sqv * rowp[h * 16 + c];
                    s += v; q2 += v * v;
                    mv = fmaxf(mv, v);
                }
                g_topv[(size_t)grow * NSUB + nt * 8 + tq * 2 + h] = mv;
            }
            s  += __shfl_down_sync(0xffffffffu, s,  2, 4);
            q2 += __shfl_down_sync(0xffffffffu, q2, 2, 4);
            s  += __shfl_down_sync(0xffffffffu, s,  1, 4);
            q2 += __shfl_down_sync(0xffffffffu, q2, 1, 4);
            if (tq == 0)
                g_part[(size_t)grow * NBLK + nt] = make_float2(s, q2);
        }
        __syncthreads();
    }
}

// ------------------------- finalize: var + exact-fp32 argmax refinement + gather -------------------------
__global__ void finalize_rows(const float* __restrict__ keys,
                              const float* __restrict__ values,
                              float* __restrict__ out) {
    int row = blockIdx.x, tid = threadIdx.x;
    __shared__ float sv[256]; __shared__ int si[256];
    __shared__ float s1[256], s2[256];
    __shared__ int clist[64]; __shared__ int ccnt;

    float2 p = g_part[(size_t)row * NBLK + tid];
    float tv[8];
    float lm = -1e30f;
    #pragma unroll
    for (int k = 0; k < 8; ++k) {
        tv[k] = g_topv[(size_t)row * NSUB + tid + k * 256];
        lm = fmaxf(lm, tv[k]);
    }
    sv[tid] = lm; s1[tid] = p.x; s2[tid] = p.y;
    if (tid == 0) ccnt = 0;
    __syncthreads();
    for (int s = 128; s > 0; s >>= 1) {
        if (tid < s) {
            s1[tid] += s1[tid + s];
            s2[tid] += s2[tid + s];
            sv[tid] = fmaxf(sv[tid], sv[tid + s]);
        }
        __syncthreads();
    }
    float M = sv[0], sum = s1[0], sumsq = s2[0];
    __syncthreads();

    float thr = M - MARGIN;
    #pragma unroll
    for (int k = 0; k < 8; ++k) {
        if (tv[k] >= thr) {
            int pos = atomicAdd(&ccnt, 1);
            if (pos < 64) clist[pos] = tid + k * 256;
        }
    }
    __syncthreads();
    int nc = min(ccnt, 64);

    // exact fp32 dots: 16 keys per candidate sub-block, 16 threads/key, coalesced
    int kg = tid >> 4;
    int lig = tid & 15;
    float bv = -1e30f; int bi = 0x7fffffff;
    const float4* qp = (const float4*)(g_qn + (size_t)row * D_);
    for (int ci = 0; ci < nc; ++ci) {
        int n = clist[ci] * 16 + kg;
        const float4* kp = (const float4*)(keys + (size_t)n * D_);
        float a0 = 0.f;
        #pragma unroll
        for (int j = 0; j < 16; ++j) {
            float4 qa = qp[j * 16 + lig], kb = kp[j * 16 + lig];
            a0 += qa.x*kb.x + qa.y*kb.y + qa.z*kb.z + qa.w*kb.w;
        }
        a0 += __shfl_xor_sync(0xffffffffu, a0, 8);
        a0 += __shfl_xor_sync(0xffffffffu, a0, 4);
        a0 += __shfl_xor_sync(0xffffffffu, a0, 2);
        a0 += __shfl_xor_sync(0xffffffffu, a0, 1);
        if (lig == 0) {
            float s = a0 * g_kinv[n];
            if (s > bv || (s == bv && n < bi)) { bv = s; bi = n; }
        }
    }
    sv[tid] = (lig == 0) ? bv : -1e30f;
    si[tid] = (lig == 0) ? bi : 0x7fffffff;
    __syncthreads();
    for (int s = 128; s > 0; s >>= 1) {
        if (tid < s) {
            if (sv[tid + s] > sv[tid] ||
                (sv[tid + s] == sv[tid] && si[tid + s] < si[tid])) {
                sv[tid] = sv[tid + s]; si[tid] = si[tid + s];
            }
        }
        __syncthreads();
    }
    int best = si[0];

    const float4* vp = (const float4*)(values + (size_t)best * D_);
    float4* op = (float4*)(out + (size_t)row * D_);
    op[tid] = vp[tid];

    if (tid == 0)
        g_var[row] = (sumsq - sum * sum * (1.0f / N_)) * (1.0f / (N_ - 1));
}

__global__ void var_mean(float* __restrict__ out, int out_size) {
    __shared__ float sh[256];
    int tid = threadIdx.x;
    float a = 0.f;
    for (int i = tid; i < B_; i += 256) a += g_var[i];
    sh[tid] = a; __syncthreads();
    for (int s = 128; s > 0; s >>= 1) { if (tid < s) sh[tid] += sh[tid + s]; __syncthreads(); }
    if (tid == 0) {
        long long base = (long long)B_ * D_;
        if (out_size > base) out[base] = sh[0] * (1.0f / B_);
    }
}

// ------------------------- launch -------------------------
extern "C" void kernel_launch(void* const* d_in, const int* in_sizes, int n_in,
                              void* d_out, int out_size) {
    const float* q = (const float*)d_in[0];
    const float* k = (const float*)d_in[1];
    const float* v = (const float*)d_in[2];
    float* out = (float*)d_out;

    const int dyn = NSTAGE * STAGE_BYTES;   // 98304
    cudaFuncSetAttribute(sim_gemm, cudaFuncAttributeMaxDynamicSharedMemorySize, dyn);

    norm_rows_q<<<B_, 256>>>(q);
    norm_rows_k<<<N_, 256>>>(k);
    dim3 g(B_ / BM, N_ / BN);     // m fastest -> K-tile reuse through L2
    sim_gemm<<<g, 256, dyn>>>();
    finalize_rows<<<B_, 256>>>(k, v, out);
    var_mean<<<1, 256>>>(out, out_size);
}

// round 9
// speedup vs baseline: 2.3065x; 2.3065x over previous
#include <cuda_runtime.h>
#include <cuda_fp16.h>
#include <cstdint>

#define B_ 4096
#define N_ 32768
#define D_ 1024
#define BM 128
#define BN 256
#define NSTAGE 4
#define KSLABS 16               // 1024 elems / 64 per slab
#define A_SLAB 16384            // 128 rows * 128B
#define B_SLAB 32768            // 256 rows * 128B
#define STAGE_BYTES (A_SLAB + B_SLAB)   // 48KB
#define NTILE (N_/BN)           // 128 n-tiles
#define NPART (NTILE*4)         // 512 partial (sum,sumsq) per row
#define NSUB (N_/16)            // 2048 16-key sub-blocks per row
#define MARGIN 0.002f

// ------------------------- scratch (no allocations allowed) -------------------------
__device__ float         g_qn[(size_t)B_*D_];     // normalized Q fp32 (refinement)
__device__ unsigned char g_qsw[(size_t)B_*D_*2];  // Q fp16, slab-contiguous SW128 layout
__device__ unsigned char g_ksw[(size_t)N_*D_*2];  // K fp16, slab-contiguous SW128 layout
__device__ float         g_kinv[N_];              // 1/||k||
__device__ float2        g_part[(size_t)B_*NPART];// per (row, nt, wc): (sum, sumsq)
__device__ float         g_topv[(size_t)B_*NSUB]; // per (row, subblock): approx max sim
__device__ float         g_var[B_];

// ------------------------- helpers -------------------------
__device__ __forceinline__ uint32_t cvta_s(const void* p) {
    return (uint32_t)__cvta_generic_to_shared(p);
}
__device__ __forceinline__ void cp_async16(uint32_t dst, const void* src) {
    asm volatile("cp.async.cg.shared.global [%0], [%1], 16;\n" :: "r"(dst), "l"(src));
}
__device__ __forceinline__ void cp_commit() {
    asm volatile("cp.async.commit_group;\n" ::: "memory");
}
template <int NN> __device__ __forceinline__ void cp_wait() {
    asm volatile("cp.async.wait_group %0;\n" :: "n"(NN) : "memory");
}
__device__ __forceinline__ void ldsm4(uint32_t& r0, uint32_t& r1, uint32_t& r2, uint32_t& r3, uint32_t a) {
    asm volatile("ldmatrix.sync.aligned.m8n8.x4.shared.b16 {%0,%1,%2,%3},[%4];\n"
        : "=r"(r0), "=r"(r1), "=r"(r2), "=r"(r3) : "r"(a));
}
__device__ __forceinline__ void mma_f16(uint32_t* c, const uint32_t* a, const uint32_t* b) {
    asm volatile("mma.sync.aligned.m16n8k16.row.col.f16.f16.f16.f16 "
        "{%0,%1},{%2,%3,%4,%5},{%6,%7},{%0,%1};\n"
        : "+r"(c[0]), "+r"(c[1])
        : "r"(a[0]), "r"(a[1]), "r"(a[2]), "r"(a[3]), "r"(b[0]), "r"(b[1]));
}
// byte offset of (row, colByte) inside an SW128 tile (128B rows)
__device__ __forceinline__ uint32_t swz(uint32_t r, uint32_t cByte) {
    return r * 128u + (cByte ^ ((r & 7u) << 4));
}

// ------------------------- normalize (writes SW128 slab-contiguous fp16) -------------------------
__global__ void norm_rows_q(const float* __restrict__ x) {
    int row = blockIdx.x, tid = threadIdx.x;
    const float4* xp = (const float4*)(x + (size_t)row * D_);
    float4 a = xp[tid];
    float ss = a.x*a.x + a.y*a.y + a.z*a.z + a.w*a.w;
    __shared__ float sh[256];
    sh[tid] = ss; __syncthreads();
    for (int s = 128; s > 0; s >>= 1) { if (tid < s) sh[tid] += sh[tid+s]; __syncthreads(); }
    float inv = 1.0f / fmaxf(sqrtf(sh[0]), 1e-12f);
    float4 o; o.x = a.x*inv; o.y = a.y*inv; o.z = a.z*inv; o.w = a.w*inv;
    ((float4*)(g_qn + (size_t)row * D_))[tid] = o;
    __half2 h0 = __floats2half2_rn(o.x, o.y);
    __half2 h1 = __floats2half2_rn(o.z, o.w);
    uint2 pk; pk.x = *(uint32_t*)&h0; pk.y = *(uint32_t*)&h1;
    int mt = row >> 7, r_in = row & 127;
    int kslab = tid >> 4;                         // 16 threads (8B each) per 128B slab row
    uint32_t cByte = (uint32_t)((tid & 15) * 8);
    uint32_t off = (uint32_t)r_in * 128u + ((cByte ^ ((uint32_t)(r_in & 7) << 4)) | (cByte & 8u));
    // note: swizzle XOR affects bits 4-6 only; cByte bit3 preserved automatically
    off = (uint32_t)r_in * 128u + (cByte ^ (((uint32_t)(r_in & 7) << 4) & 0x70u));
    *(uint2*)(g_qsw + (size_t)(mt * KSLABS + kslab) * A_SLAB + off) = pk;
}

__global__ void norm_rows_k(const float* __restrict__ x) {
    int row = blockIdx.x, tid = threadIdx.x;
    const float4* xp = (const float4*)(x + (size_t)row * D_);
    float4 a = xp[tid];
    float ss = a.x*a.x + a.y*a.y + a.z*a.z + a.w*a.w;
    __shared__ float sh[256];
    sh[tid] = ss; __syncthreads();
    for (int s = 128; s > 0; s >>= 1) { if (tid < s) sh[tid] += sh[tid+s]; __syncthreads(); }
    float inv = 1.0f / fmaxf(sqrtf(sh[0]), 1e-12f);
    if (tid == 0) g_kinv[row] = inv;
    float4 o; o.x = a.x*inv; o.y = a.y*inv; o.z = a.z*inv; o.w = a.w*inv;
    __half2 h0 = __floats2half2_rn(o.x, o.y);
    __half2 h1 = __floats2half2_rn(o.z, o.w);
    uint2 pk; pk.x = *(uint32_t*)&h0; pk.y = *(uint32_t*)&h1;
    int nt = row >> 8, r_in = row & 255;
    int kslab = tid >> 4;
    uint32_t cByte = (uint32_t)((tid & 15) * 8);
    uint32_t off = (uint32_t)r_in * 128u + (cByte ^ (((uint32_t)(r_in & 7) << 4) & 0x70u));
    *(uint2*)(g_ksw + (size_t)(nt * KSLABS + kslab) * B_SLAB + off) = pk;
}

// ------------------------- GEMM: f16 mma.sync (f16 acc), 128x256 tile, reg epilogue -------------------------
__global__ __launch_bounds__(256, 1) void sim_gemm() {
    extern __shared__ __align__(16) unsigned char smraw[];   // NSTAGE * 48KB

    const int tid = threadIdx.x;
    const int lane = tid & 31, warp = tid >> 5;
    const int wr = warp >> 2;            // 2 warp-rows of 64
    const int wc = warp & 3;             // 4 warp-cols of 64
    const int wm = wr * 64;
    const int mt = blockIdx.x;
    const int nt = blockIdx.y;

    const unsigned char* qbase = g_qsw + (size_t)mt * KSLABS * A_SLAB;
    const unsigned char* kbase = g_ksw + (size_t)nt * KSLABS * B_SLAB;
    const uint32_t sbase = cvta_s(smraw);

    uint32_t acc[4][8][2];
    #pragma unroll
    for (int i = 0; i < 4; i++)
        #pragma unroll
        for (int j = 0; j < 8; j++) { acc[i][j][0] = 0u; acc[i][j][1] = 0u; }

    // prologue: slabs 0..2 into stages 0..2
    #pragma unroll
    for (int s = 0; s < NSTAGE - 1; ++s) {
        uint32_t st = sbase + s * STAGE_BYTES;
        #pragma unroll
        for (int i = 0; i < 4; ++i) {
            uint32_t o = (uint32_t)(i * 4096 + tid * 16);
            cp_async16(st + o, qbase + (size_t)s * A_SLAB + o);
        }
        #pragma unroll
        for (int i = 0; i < 8; ++i) {
            uint32_t o = (uint32_t)(i * 4096 + tid * 16);
            cp_async16(st + A_SLAB + o, kbase + (size_t)s * B_SLAB + o);
        }
        cp_commit();
    }

    const uint32_t rsel = lane & 15;
    const uint32_t cbase = (uint32_t)((lane >> 4) << 4);   // 0 or 16 bytes

    #pragma unroll 1
    for (int t = 0; t < KSLABS; ++t) {
        cp_wait<NSTAGE - 2>();
        __syncthreads();
        if (t + NSTAGE - 1 < KSLABS) {
            int s2 = (t + NSTAGE - 1) & (NSTAGE - 1);
            uint32_t st = sbase + s2 * STAGE_BYTES;
            #pragma unroll
            for (int i = 0; i < 4; ++i) {
                uint32_t o = (uint32_t)(i * 4096 + tid * 16);
                cp_async16(st + o, qbase + (size_t)(t + NSTAGE - 1) * A_SLAB + o);
            }
            #pragma unroll
            for (int i = 0; i < 8; ++i) {
                uint32_t o = (uint32_t)(i * 4096 + tid * 16);
                cp_async16(st + A_SLAB + o, kbase + (size_t)(t + NSTAGE - 1) * B_SLAB + o);
            }
        }
        cp_commit();

        uint32_t sA = sbase + (t & (NSTAGE - 1)) * STAGE_BYTES;
        uint32_t sB = sA + A_SLAB;
        #pragma unroll
        for (int kk = 0; kk < 4; ++kk) {
            uint32_t cByte = (uint32_t)(kk * 32) + cbase;
            uint32_t af[4][4], bf[8][2];
            #pragma unroll
            for (int mi = 0; mi < 4; ++mi)
                ldsm4(af[mi][0], af[mi][1], af[mi][2], af[mi][3],
                      sA + swz(wm + mi * 16 + rsel, cByte));
            #pragma unroll
            for (int g = 0; g < 4; ++g) {
                uint32_t r0, r1, r2, r3;
                ldsm4(r0, r1, r2, r3, sB + swz(wc * 64 + g * 16 + rsel, cByte));
                bf[g*2+0][0] = r0; bf[g*2+0][1] = r2;
                bf[g*2+1][0] = r1; bf[g*2+1][1] = r3;
            }
            #pragma unroll
            for (int mi = 0; mi < 4; ++mi)
                #pragma unroll
                for (int ni = 0; ni < 8; ++ni)
                    mma_f16(acc[mi][ni], af[mi], bf[ni]);
        }
    }

    // register epilogue: width-4 shuffles; no smem, no syncthreads
    const int rq = lane >> 2;            // row-in-16 quarter
    const int lq = lane & 3;             // col quarter within 8-col group
    #pragma unroll
    for (int mi = 0; mi < 4; ++mi) {
        float s0 = 0.f, q0 = 0.f, s1 = 0.f, q1 = 0.f;
        float tv0[4], tv1[4];
        #pragma unroll
        for (int sb = 0; sb < 4; ++sb) {
            float m0 = -1e30f, m1 = -1e30f;
            #pragma unroll
            for (int j = 0; j < 2; ++j) {
                int ni = sb * 2 + j;
                float2 f0 = __half22float2(*(__half2*)&acc[mi][ni][0]);
                float2 f1 = __half22float2(*(__half2*)&acc[mi][ni][1]);
                s0 += f0.x + f0.y; q0 += f0.x*f0.x + f0.y*f0.y;
                m0 = fmaxf(m0, fmaxf(f0.x, f0.y));
                s1 += f1.x + f1.y; q1 += f1.x*f1.x + f1.y*f1.y;
                m1 = fmaxf(m1, fmaxf(f1.x, f1.y));
            }
            m0 = fmaxf(m0, __shfl_xor_sync(0xffffffffu, m0, 1, 4));
            m0 = fmaxf(m0, __shfl_xor_sync(0xffffffffu, m0, 2, 4));
            m1 = fmaxf(m1, __shfl_xor_sync(0xffffffffu, m1, 1, 4));
            m1 = fmaxf(m1, __shfl_xor_sync(0xffffffffu, m1, 2, 4));
            tv0[sb] = m0; tv1[sb] = m1;
        }
        s0 += __shfl_xor_sync(0xffffffffu, s0, 1, 4);
        s0 += __shfl_xor_sync(0xffffffffu, s0, 2, 4);
        q0 += __shfl_xor_sync(0xffffffffu, q0, 1, 4);
        q0 += __shfl_xor_sync(0xffffffffu, q0, 2, 4);
        s1 += __shfl_xor_sync(0xffffffffu, s1, 1, 4);
        s1 += __shfl_xor_sync(0xffffffffu, s1, 2, 4);
        q1 += __shfl_xor_sync(0xffffffffu, q1, 1, 4);
        q1 += __shfl_xor_sync(0xffffffffu, q1, 2, 4);
        if (lq == 0) {
            int row0 = mt * BM + wm + mi * 16 + rq;
            int row1 = row0 + 8;
            *(float4*)&g_topv[(size_t)row0 * NSUB + nt * 16 + wc * 4] =
                make_float4(tv0[0], tv0[1], tv0[2], tv0[3]);
            *(float4*)&g_topv[(size_t)row1 * NSUB + nt * 16 + wc * 4] =
                make_float4(tv1[0], tv1[1], tv1[2], tv1[3]);
            g_part[(size_t)row0 * NPART + nt * 4 + wc] = make_float2(s0, q0);
            g_part[(size_t)row1 * NPART + nt * 4 + wc] = make_float2(s1, q1);
        }
    }
}

// ------------------------- finalize: warp per row -------------------------
__global__ __launch_bounds__(256) void finalize_rows(const float* __restrict__ keys,
                                                     const float* __restrict__ values,
                                                     float* __restrict__ out) {
    const int wid = threadIdx.x >> 5, lane = threadIdx.x & 31;
    const int row = blockIdx.x * 8 + wid;
    __shared__ int cl[8][16];
    __shared__ int cnt[8];

    const float4* tp = (const float4*)(g_topv + (size_t)row * NSUB);   // 512 float4
    float lm = -1e30f;
    #pragma unroll
    for (int i = 0; i < 16; ++i) {
        float4 t = tp[i * 32 + lane];
        lm = fmaxf(lm, fmaxf(fmaxf(t.x, t.y), fmaxf(t.z, t.w)));
    }
    #pragma unroll
    for (int d = 16; d > 0; d >>= 1)
        lm = fmaxf(lm, __shfl_xor_sync(0xffffffffu, lm, d));

    const float2* pp = (const float2*)(g_part + (size_t)row * NPART);  // 512 float2
    float s = 0.f, q2 = 0.f;
    #pragma unroll
    for (int i = 0; i < 16; ++i) {
        float2 p = pp[i * 32 + lane];
        s += p.x; q2 += p.y;
    }
    #pragma unroll
    for (int d = 16; d > 0; d >>= 1) {
        s  += __shfl_xor_sync(0xffffffffu, s,  d);
        q2 += __shfl_xor_sync(0xffffffffu, q2, d);
    }

    if (lane == 0) cnt[wid] = 0;
    __syncwarp();
    float thr = lm - MARGIN;
    #pragma unroll
    for (int i = 0; i < 16; ++i) {
        float4 t = tp[i * 32 + lane];
        int base = (i * 32 + lane) * 4;
        if (t.x >= thr) { int p = atomicAdd(&cnt[wid], 1); if (p < 16) cl[wid][p] = base; }
        if (t.y >= thr) { int p = atomicAdd(&cnt[wid], 1); if (p < 16) cl[wid][p] = base + 1; }
        if (t.z >= thr) { int p = atomicAdd(&cnt[wid], 1); if (p < 16) cl[wid][p] = base + 2; }
        if (t.w >= thr) { int p = atomicAdd(&cnt[wid], 1); if (p < 16) cl[wid][p] = base + 3; }
    }
    __syncwarp();
    int nc = min(cnt[wid], 16);

    // exact fp32 refinement: warp-cooperative dot per candidate key
    float bv = -1e30f; int bi = 0x7fffffff;
    const float4* qp = (const float4*)(g_qn + (size_t)row * D_);
    for (int ci = 0; ci < nc; ++ci) {
        int sb = cl[wid][ci];
        #pragma unroll 1
        for (int kx = 0; kx < 16; ++kx) {
            int n = sb * 16 + kx;
            const float4* kp = (const float4*)(keys + (size_t)n * D_);
            float a0 = 0.f;
            #pragma unroll
            for (int j = 0; j < 8; ++j) {
                float4 qa = qp[j * 32 + lane], kb = kp[j * 32 + lane];
                a0 += qa.x*kb.x + qa.y*kb.y + qa.z*kb.z + qa.w*kb.w;
            }
            #pragma unroll
            for (int d = 16; d > 0; d >>= 1)
                a0 += __shfl_xor_sync(0xffffffffu, a0, d);
            float sv = a0 * g_kinv[n];
            if (sv > bv || (sv == bv && n < bi)) { bv = sv; bi = n; }
        }
    }

    const float4* vp = (const float4*)(values + (size_t)bi * D_);
    float4* op = (float4*)(out + (size_t)row * D_);
    #pragma unroll
    for (int j = 0; j < 8; ++j) op[j * 32 + lane] = vp[j * 32 + lane];

    if (lane == 0)
        g_var[row] = (q2 - s * s * (1.0f / N_)) * (1.0f / (N_ - 1));
}

__global__ void var_mean(float* __restrict__ out, int out_size) {
    __shared__ float sh[256];
    int tid = threadIdx.x;
    float a = 0.f;
    for (int i = tid; i < B_; i += 256) a += g_var[i];
    sh[tid] = a; __syncthreads();
    for (int s = 128; s > 0; s >>= 1) { if (tid < s) sh[tid] += sh[tid + s]; __syncthreads(); }
    if (tid == 0) {
        long long base = (long long)B_ * D_;
        if (out_size > base) out[base] = sh[0] * (1.0f / B_);
    }
}

// ------------------------- launch -------------------------
extern "C" void kernel_launch(void* const* d_in, const int* in_sizes, int n_in,
                              void* d_out, int out_size) {
    const float* q = (const float*)d_in[0];
    const float* k = (const float*)d_in[1];
    const float* v = (const float*)d_in[2];
    float* out = (float*)d_out;

    const int dyn = NSTAGE * STAGE_BYTES;   // 196608
    cudaFuncSetAttribute(sim_gemm, cudaFuncAttributeMaxDynamicSharedMemorySize, dyn);

    norm_rows_q<<<B_, 256>>>(q);
    norm_rows_k<<<N_, 256>>>(k);
    dim3 g(B_ / BM, N_ / BN);     // m fastest -> K-tile reuse through L2
    sim_gemm<<<g, 256, dyn>>>();
    finalize_rows<<<B_ / 8, 256>>>(k, v, out);
    var_mean<<<1, 256>>>(out, out_size);
}

// round 11
// speedup vs baseline: 2.4341x; 1.0553x over previous
#include <cuda_runtime.h>
#include <cuda_fp16.h>
#include <cstdint>

#define B_ 4096
#define N_ 32768
#define D_ 1024
#define BM 128
#define BN 256
#define NSTAGE 4
#define KSLABS 16               // 1024 elems / 64 per slab
#define A_SLAB 16384            // 128 rows * 128B
#define B_SLAB 32768            // 256 rows * 128B
#define STAGE_BYTES (A_SLAB + B_SLAB)   // 48KB
#define NBLKS 512               // 64-key blocks per row
#define MARGIN 0.002f

// ------------------------- scratch (no allocations allowed) -------------------------
__device__ float         g_qn[(size_t)B_*D_];     // normalized Q fp32 (refinement)
__device__ unsigned char g_qsw[(size_t)B_*D_*2];  // Q fp16, slab-contiguous SW128 layout
__device__ unsigned char g_ksw[(size_t)N_*D_*2];  // K fp16, slab-contiguous SW128 layout
__device__ float         g_kinv[N_];              // 1/||k||
__device__ float4        g_blk[(size_t)B_*NBLKS]; // per 64-key block: (max, m2|idx, sum, sumsq)
__device__ float         g_var[B_];

// ------------------------- helpers -------------------------
__device__ __forceinline__ uint32_t cvta_s(const void* p) {
    return (uint32_t)__cvta_generic_to_shared(p);
}
__device__ __forceinline__ void cp_async16(uint32_t dst, const void* src) {
    asm volatile("cp.async.cg.shared.global [%0], [%1], 16;\n" :: "r"(dst), "l"(src));
}
__device__ __forceinline__ void cp_commit() {
    asm volatile("cp.async.commit_group;\n" ::: "memory");
}
template <int NN> __device__ __forceinline__ void cp_wait() {
    asm volatile("cp.async.wait_group %0;\n" :: "n"(NN) : "memory");
}
__device__ __forceinline__ void ldsm4(uint32_t& r0, uint32_t& r1, uint32_t& r2, uint32_t& r3, uint32_t a) {
    asm volatile("ldmatrix.sync.aligned.m8n8.x4.shared.b16 {%0,%1,%2,%3},[%4];\n"
        : "=r"(r0), "=r"(r1), "=r"(r2), "=r"(r3) : "r"(a));
}
__device__ __forceinline__ void mma_f16(uint32_t* c, const uint32_t* a, const uint32_t* b) {
    asm volatile("mma.sync.aligned.m16n8k16.row.col.f16.f16.f16.f16 "
        "{%0,%1},{%2,%3,%4,%5},{%6,%7},{%0,%1};\n"
        : "+r"(c[0]), "+r"(c[1])
        : "r"(a[0]), "r"(a[1]), "r"(a[2]), "r"(a[3]), "r"(b[0]), "r"(b[1]));
}
__device__ __forceinline__ uint32_t swz(uint32_t r, uint32_t cByte) {
    return r * 128u + (cByte ^ ((r & 7u) << 4));
}

// ------------------------- normalize (writes SW128 slab-contiguous fp16) -------------------------
__global__ void norm_rows_q(const float* __restrict__ x) {
    int row = blockIdx.x, tid = threadIdx.x;
    const float4* xp = (const float4*)(x + (size_t)row * D_);
    float4 a = xp[tid];
    float ss = a.x*a.x + a.y*a.y + a.z*a.z + a.w*a.w;
    __shared__ float sh[256];
    sh[tid] = ss; __syncthreads();
    for (int s = 128; s > 0; s >>= 1) { if (tid < s) sh[tid] += sh[tid+s]; __syncthreads(); }
    float inv = 1.0f / fmaxf(sqrtf(sh[0]), 1e-12f);
    float4 o; o.x = a.x*inv; o.y = a.y*inv; o.z = a.z*inv; o.w = a.w*inv;
    ((float4*)(g_qn + (size_t)row * D_))[tid] = o;
    __half2 h0 = __floats2half2_rn(o.x, o.y);
    __half2 h1 = __floats2half2_rn(o.z, o.w);
    uint2 pk; pk.x = *(uint32_t*)&h0; pk.y = *(uint32_t*)&h1;
    int mt = row >> 7, r_in = row & 127;
    int kslab = tid >> 4;
    uint32_t cByte = (uint32_t)((tid & 15) * 8);
    uint32_t off = (uint32_t)r_in * 128u + (cByte ^ (((uint32_t)(r_in & 7) << 4) & 0x70u));
    *(uint2*)(g_qsw + (size_t)(mt * KSLABS + kslab) * A_SLAB + off) = pk;
}

__global__ void norm_rows_k(const float* __restrict__ x) {
    int row = blockIdx.x, tid = threadIdx.x;
    const float4* xp = (const float4*)(x + (size_t)row * D_);
    float4 a = xp[tid];
    float ss = a.x*a.x + a.y*a.y + a.z*a.z + a.w*a.w;
    __shared__ float sh[256];
    sh[tid] = ss; __syncthreads();
    for (int s = 128; s > 0; s >>= 1) { if (tid < s) sh[tid] += sh[tid+s]; __syncthreads(); }
    float inv = 1.0f / fmaxf(sqrtf(sh[0]), 1e-12f);
    if (tid == 0) g_kinv[row] = inv;
    float4 o; o.x = a.x*inv; o.y = a.y*inv; o.z = a.z*inv; o.w = a.w*inv;
    __half2 h0 = __floats2half2_rn(o.x, o.y);
    __half2 h1 = __floats2half2_rn(o.z, o.w);
    uint2 pk; pk.x = *(uint32_t*)&h0; pk.y = *(uint32_t*)&h1;
    int nt = row >> 8, r_in = row & 255;
    int kslab = tid >> 4;
    uint32_t cByte = (uint32_t)((tid & 15) * 8);
    uint32_t off = (uint32_t)r_in * 128u + (cByte ^ (((uint32_t)(r_in & 7) << 4) & 0x70u));
    *(uint2*)(g_ksw + (size_t)(nt * KSLABS + kslab) * B_SLAB + off) = pk;
}

// ------------------------- GEMM: f16 mma.sync, frag double-buffer, top2 epilogue -------------------------
__global__ __launch_bounds__(256, 1) void sim_gemm() {
    extern __shared__ __align__(16) unsigned char smraw[];   // NSTAGE * 48KB

    const int tid = threadIdx.x;
    const int lane = tid & 31, warp = tid >> 5;
    const int wr = warp >> 2;            // 2 warp-rows of 64
    const int wc = warp & 3;             // 4 warp-cols of 64
    const int wm = wr * 64;
    const int mt = blockIdx.x;
    const int nt = blockIdx.y;

    const unsigned char* qbase = g_qsw + (size_t)mt * KSLABS * A_SLAB;
    const unsigned char* kbase = g_ksw + (size_t)nt * KSLABS * B_SLAB;
    const uint32_t sbase = cvta_s(smraw);

    uint32_t acc[4][8][2];
    #pragma unroll
    for (int i = 0; i < 4; i++)
        #pragma unroll
        for (int j = 0; j < 8; j++) { acc[i][j][0] = 0u; acc[i][j][1] = 0u; }

    // prologue: slabs 0..2 into stages 0..2
    #pragma unroll
    for (int s = 0; s < NSTAGE - 1; ++s) {
        uint32_t st = sbase + s * STAGE_BYTES;
        #pragma unroll
        for (int i = 0; i < 4; ++i) {
            uint32_t o = (uint32_t)(i * 4096 + tid * 16);
            cp_async16(st + o, qbase + (size_t)s * A_SLAB + o);
        }
        #pragma unroll
        for (int i = 0; i < 8; ++i) {
            uint32_t o = (uint32_t)(i * 4096 + tid * 16);
            cp_async16(st + A_SLAB + o, kbase + (size_t)s * B_SLAB + o);
        }
        cp_commit();
    }

    const uint32_t rsel = lane & 15;
    const uint32_t cbase = (uint32_t)((lane >> 4) << 4);   // 0 or 16 bytes

    uint32_t af[2][4][4], bf[2][8][2];

    #pragma unroll 1
    for (int t = 0; t < KSLABS; ++t) {
        cp_wait<NSTAGE - 2>();
        __syncthreads();
        if (t + NSTAGE - 1 < KSLABS) {
            int s2 = (t + NSTAGE - 1) & (NSTAGE - 1);
            uint32_t st = sbase + s2 * STAGE_BYTES;
            #pragma unroll
            for (int i = 0; i < 4; ++i) {
                uint32_t o = (uint32_t)(i * 4096 + tid * 16);
                cp_async16(st + o, qbase + (size_t)(t + NSTAGE - 1) * A_SLAB + o);
            }
            #pragma unroll
            for (int i = 0; i < 8; ++i) {
                uint32_t o = (uint32_t)(i * 4096 + tid * 16);
                cp_async16(st + A_SLAB + o, kbase + (size_t)(t + NSTAGE - 1) * B_SLAB + o);
            }
        }
        cp_commit();

        uint32_t sA = sbase + (t & (NSTAGE - 1)) * STAGE_BYTES;
        uint32_t sB = sA + A_SLAB;

        // preload kk=0 fragments into buffer 0
        {
            uint32_t cByte = cbase;
            #pragma unroll
            for (int mi = 0; mi < 4; ++mi)
                ldsm4(af[0][mi][0], af[0][mi][1], af[0][mi][2], af[0][mi][3],
                      sA + swz(wm + mi * 16 + rsel, cByte));
            #pragma unroll
            for (int g = 0; g < 4; ++g) {
                uint32_t r0, r1, r2, r3;
                ldsm4(r0, r1, r2, r3, sB + swz(wc * 64 + g * 16 + rsel, cByte));
                bf[0][g*2+0][0] = r0; bf[0][g*2+0][1] = r2;
                bf[0][g*2+1][0] = r1; bf[0][g*2+1][1] = r3;
            }
        }
        #pragma unroll
        for (int kk = 0; kk < 4; ++kk) {
            int cur = kk & 1;
            if (kk < 3) {
                int nxt = cur ^ 1;
                uint32_t cByte = (uint32_t)((kk + 1) * 32) + cbase;
                #pragma unroll
                for (int mi = 0; mi < 4; ++mi)
                    ldsm4(af[nxt][mi][0], af[nxt][mi][1], af[nxt][mi][2], af[nxt][mi][3],
                          sA + swz(wm + mi * 16 + rsel, cByte));
                #pragma unroll
                for (int g = 0; g < 4; ++g) {
                    uint32_t r0, r1, r2, r3;
                    ldsm4(r0, r1, r2, r3, sB + swz(wc * 64 + g * 16 + rsel, cByte));
                    bf[nxt][g*2+0][0] = r0; bf[nxt][g*2+0][1] = r2;
                    bf[nxt][g*2+1][0] = r1; bf[nxt][g*2+1][1] = r3;
                }
            }
            #pragma unroll
            for (int mi = 0; mi < 4; ++mi)
                #pragma unroll
                for (int ni = 0; ni < 8; ++ni)
                    mma_f16(acc[mi][ni], af[cur][mi], bf[cur][ni]);
        }
    }

    // register epilogue: per (row, 64-col warp tile) -> (max, runnerup|idx, sum, sumsq)
    const int rq = lane >> 2;            // row within 8
    const int lq = lane & 3;             // col quarter
    #pragma unroll
    for (int mi = 0; mi < 4; ++mi) {
        #pragma unroll
        for (int r = 0; r < 2; ++r) {
            float m1 = -1e30f, m2 = -1e30f; int i1 = 0;
            float s = 0.f, q = 0.f;
            #pragma unroll
            for (int ni = 0; ni < 8; ++ni) {
                float2 f = __half22float2(*(__half2*)&acc[mi][ni][r]);
                int c = ni * 8 + lq * 2;
                if (f.x > m1) { m2 = m1; m1 = f.x; i1 = c; } else m2 = fmaxf(m2, f.x);
                if (f.y > m1) { m2 = m1; m1 = f.y; i1 = c + 1; } else m2 = fmaxf(m2, f.y);
                s += f.x + f.y;
                q = fmaf(f.x, f.x, q); q = fmaf(f.y, f.y, q);
            }
            #pragma unroll
            for (int d = 1; d <= 2; d <<= 1) {
                float om1 = __shfl_xor_sync(0xffffffffu, m1, d, 4);
                float om2 = __shfl_xor_sync(0xffffffffu, m2, d, 4);
                int   oi  = __shfl_xor_sync(0xffffffffu, i1, d, 4);
                if (om1 > m1) { m2 = fmaxf(m1, om2); m1 = om1; i1 = oi; }
                else          { m2 = fmaxf(m2, om1); }
                s += __shfl_xor_sync(0xffffffffu, s, d, 4);
                q += __shfl_xor_sync(0xffffffffu, q, d, 4);
            }
            if (lq == 0) {
                int row = mt * BM + wm + mi * 16 + rq + r * 8;
                uint32_t pb = (__float_as_uint(m2) & ~63u) | (uint32_t)i1;
                g_blk[(size_t)row * NBLKS + nt * 4 + wc] =
                    make_float4(m1, __uint_as_float(pb), s, q);
            }
        }
    }
}

// ------------------------- finalize: warp per row, key-granular refinement -------------------------
__global__ __launch_bounds__(256) void finalize_rows(const float* __restrict__ keys,
                                                     const float* __restrict__ values,
                                                     float* __restrict__ out) {
    const int wid = threadIdx.x >> 5, lane = threadIdx.x & 31;
    const int row = blockIdx.x * 8 + wid;
    __shared__ int klist[8][16];
    __shared__ int blist[8][4];
    __shared__ int kcnt[8], bcnt[8];

    const float4* bp = (const float4*)g_blk + (size_t)row * NBLKS;
    float lm = -1e30f, s = 0.f, q2 = 0.f;
    #pragma unroll
    for (int i = 0; i < 16; ++i) {
        float4 b = bp[i * 32 + lane];
        lm = fmaxf(lm, b.x); s += b.z; q2 += b.w;
    }
    #pragma unroll
    for (int d = 16; d > 0; d >>= 1) {
        lm = fmaxf(lm, __shfl_xor_sync(0xffffffffu, lm, d));
        s  += __shfl_xor_sync(0xffffffffu, s,  d);
        q2 += __shfl_xor_sync(0xffffffffu, q2, d);
    }
    if (lane == 0) { kcnt[wid] = 0; bcnt[wid] = 0; }
    __syncwarp();
    float thr = lm - MARGIN;
    #pragma unroll
    for (int i = 0; i < 16; ++i) {
        float4 b = bp[i * 32 + lane];
        if (b.x >= thr) {
            int blk = i * 32 + lane;
            uint32_t pb = __float_as_uint(b.y);
            int p = atomicAdd(&kcnt[wid], 1);
            if (p < 16) klist[wid][p] = blk * 64 + (int)(pb & 63u);
            if (b.y >= thr) {             // runner-up also near max -> masking risk: refine whole block
                int p2 = atomicAdd(&bcnt[wid], 1);
                if (p2 < 4) blist[wid][p2] = blk;
            }
        }
    }
    __syncwarp();
    int nk = min(kcnt[wid], 16), nb = min(bcnt[wid], 4);

    float bv = -1e30f; int bi = 0x7fffffff;
    const float4* qp = (const float4*)(g_qn + (size_t)row * D_);
    for (int ci = 0; ci < nk; ++ci) {
        int n = klist[wid][ci];
        const float4* kp = (const float4*)(keys + (size_t)n * D_);
        float a0 = 0.f;
        #pragma unroll
        for (int j = 0; j < 8; ++j) {
            float4 qa = qp[j * 32 + lane], kb = kp[j * 32 + lane];
            a0 += qa.x*kb.x + qa.y*kb.y + qa.z*kb.z + qa.w*kb.w;
        }
        #pragma unroll
        for (int d = 16; d > 0; d >>= 1) a0 += __shfl_xor_sync(0xffffffffu, a0, d);
        float sv = a0 * g_kinv[n];
        if (sv > bv || (sv == bv && n < bi)) { bv = sv; bi = n; }
    }
    for (int ci = 0; ci < nb; ++ci) {
        int n0 = blist[wid][ci] * 64;
        #pragma unroll 1
        for (int kx = 0; kx < 64; ++kx) {
            int n = n0 + kx;
            const float4* kp = (const float4*)(keys + (size_t)n * D_);
            float a0 = 0.f;
            #pragma unroll
            for (int j = 0; j < 8; ++j) {
                float4 qa = qp[j * 32 + lane], kb = kp[j * 32 + lane];
                a0 += qa.x*kb.x + qa.y*kb.y + qa.z*kb.z + qa.w*kb.w;
            }
            #pragma unroll
            for (int d = 16; d > 0; d >>= 1) a0 += __shfl_xor_sync(0xffffffffu, a0, d);
            float sv = a0 * g_kinv[n];
            if (sv > bv || (sv == bv && n < bi)) { bv = sv; bi = n; }
        }
    }

    const float4* vp = (const float4*)(values + (size_t)bi * D_);
    float4* op = (float4*)(out + (size_t)row * D_);
    #pragma unroll
    for (int j = 0; j < 8; ++j) op[j * 32 + lane] = vp[j * 32 + lane];

    if (lane == 0)
        g_var[row] = (q2 - s * s * (1.0f / N_)) * (1.0f / (N_ - 1));
}

__global__ void var_mean(float* __restrict__ out, int out_size) {
    __shared__ float sh[256];
    int tid = threadIdx.x;
    float a = 0.f;
    for (int i = tid; i < B_; i += 256) a += g_var[i];
    sh[tid] = a; __syncthreads();
    for (int s = 128; s > 0; s >>= 1) { if (tid < s) sh[tid] += sh[tid + s]; __syncthreads(); }
    if (tid == 0) {
        long long base = (long long)B_ * D_;
        if (out_size > base) out[base] = sh[0] * (1.0f / B_);
    }
}

// ------------------------- launch -------------------------
extern "C" void kernel_launch(void* const* d_in, const int* in_sizes, int n_in,
                              void* d_out, int out_size) {
    const float* q = (const float*)d_in[0];
    const float* k = (const float*)d_in[1];
    const float* v = (const float*)d_in[2];
    float* out = (float*)d_out;

    const int dyn = NSTAGE * STAGE_BYTES;   // 196608
    cudaFuncSetAttribute(sim_gemm, cudaFuncAttributeMaxDynamicSharedMemorySize, dyn);

    norm_rows_q<<<B_, 256>>>(q);
    norm_rows_k<<<N_, 256>>>(k);
    dim3 g(B_ / BM, N_ / BN);     // m fastest -> K-tile reuse through L2
    sim_gemm<<<g, 256, dyn>>>();
    finalize_rows<<<B_ / 8, 256>>>(k, v, out);
    var_mean<<<1, 256>>>(out, out_size);
}

// round 12
// speedup vs baseline: 2.4747x; 1.0167x over previous
#include <cuda_runtime.h>
#include <cuda_fp16.h>
#include <cstdint>

#define B_ 4096
#define N_ 32768
#define D_ 1024
#define BM 256
#define BN 256
#define NSTAGE 3
#define KSLABS 16               // 1024 elems / 64 per slab
#define A_SLAB 32768            // 256 rows * 128B
#define B_SLAB 32768            // 256 rows * 128B
#define STAGE_BYTES (A_SLAB + B_SLAB)   // 64KB
#define NBLKS 512               // 64-key blocks per row
#define MARGIN 0.002f

// ------------------------- scratch (no allocations allowed) -------------------------
__device__ float         g_qn[(size_t)B_*D_];     // normalized Q fp32 (refinement)
__device__ unsigned char g_qsw[(size_t)B_*D_*2];  // Q fp16, slab-contiguous SW128 layout
__device__ unsigned char g_ksw[(size_t)N_*D_*2];  // K fp16, slab-contiguous SW128 layout
__device__ float         g_kinv[N_];              // 1/||k||
__device__ float4        g_blk[(size_t)B_*NBLKS]; // per 64-key block: (max, m2|idx, sum, sumsq)
__device__ float         g_var[B_];

// ------------------------- helpers -------------------------
__device__ __forceinline__ uint32_t cvta_s(const void* p) {
    return (uint32_t)__cvta_generic_to_shared(p);
}
__device__ __forceinline__ void cp_async16(uint32_t dst, const void* src) {
    asm volatile("cp.async.cg.shared.global [%0], [%1], 16;\n" :: "r"(dst), "l"(src));
}
__device__ __forceinline__ void cp_commit() {
    asm volatile("cp.async.commit_group;\n" ::: "memory");
}
template <int NN> __device__ __forceinline__ void cp_wait() {
    asm volatile("cp.async.wait_group %0;\n" :: "n"(NN) : "memory");
}
__device__ __forceinline__ void ldsm4(uint32_t& r0, uint32_t& r1, uint32_t& r2, uint32_t& r3, uint32_t a) {
    asm volatile("ldmatrix.sync.aligned.m8n8.x4.shared.b16 {%0,%1,%2,%3},[%4];\n"
        : "=r"(r0), "=r"(r1), "=r"(r2), "=r"(r3) : "r"(a));
}
__device__ __forceinline__ void mma_f16(uint32_t* c, const uint32_t* a, const uint32_t* b) {
    asm volatile("mma.sync.aligned.m16n8k16.row.col.f16.f16.f16.f16 "
        "{%0,%1},{%2,%3,%4,%5},{%6,%7},{%0,%1};\n"
        : "+r"(c[0]), "+r"(c[1])
        : "r"(a[0]), "r"(a[1]), "r"(a[2]), "r"(a[3]), "r"(b[0]), "r"(b[1]));
}
__device__ __forceinline__ uint32_t swz(uint32_t r, uint32_t cByte) {
    return r * 128u + (cByte ^ ((r & 7u) << 4));
}

// ------------------------- normalize (writes SW128 slab-contiguous fp16) -------------------------
__global__ void norm_rows_q(const float* __restrict__ x) {
    int row = blockIdx.x, tid = threadIdx.x;
    const float4* xp = (const float4*)(x + (size_t)row * D_);
    float4 a = xp[tid];
    float ss = a.x*a.x + a.y*a.y + a.z*a.z + a.w*a.w;
    __shared__ float sh[256];
    sh[tid] = ss; __syncthreads();
    for (int s = 128; s > 0; s >>= 1) { if (tid < s) sh[tid] += sh[tid+s]; __syncthreads(); }
    float inv = 1.0f / fmaxf(sqrtf(sh[0]), 1e-12f);
    float4 o; o.x = a.x*inv; o.y = a.y*inv; o.z = a.z*inv; o.w = a.w*inv;
    ((float4*)(g_qn + (size_t)row * D_))[tid] = o;
    __half2 h0 = __floats2half2_rn(o.x, o.y);
    __half2 h1 = __floats2half2_rn(o.z, o.w);
    uint2 pk; pk.x = *(uint32_t*)&h0; pk.y = *(uint32_t*)&h1;
    int mt = row >> 8, r_in = row & 255;
    int kslab = tid >> 4;
    uint32_t cByte = (uint32_t)((tid & 15) * 8);
    uint32_t off = (uint32_t)r_in * 128u + (cByte ^ (((uint32_t)(r_in & 7) << 4) & 0x70u));
    *(uint2*)(g_qsw + (size_t)(mt * KSLABS + kslab) * A_SLAB + off) = pk;
}

__global__ void norm_rows_k(const float* __restrict__ x) {
    int row = blockIdx.x, tid = threadIdx.x;
    const float4* xp = (const float4*)(x + (size_t)row * D_);
    float4 a = xp[tid];
    float ss = a.x*a.x + a.y*a.y + a.z*a.z + a.w*a.w;
    __shared__ float sh[256];
    sh[tid] = ss; __syncthreads();
    for (int s = 128; s > 0; s >>= 1) { if (tid < s) sh[tid] += sh[tid+s]; __syncthreads(); }
    float inv = 1.0f / fmaxf(sqrtf(sh[0]), 1e-12f);
    if (tid == 0) g_kinv[row] = inv;
    float4 o; o.x = a.x*inv; o.y = a.y*inv; o.z = a.z*inv; o.w = a.w*inv;
    __half2 h0 = __floats2half2_rn(o.x, o.y);
    __half2 h1 = __floats2half2_rn(o.z, o.w);
    uint2 pk; pk.x = *(uint32_t*)&h0; pk.y = *(uint32_t*)&h1;
    int nt = row >> 8, r_in = row & 255;
    int kslab = tid >> 4;
    uint32_t cByte = (uint32_t)((tid & 15) * 8);
    uint32_t off = (uint32_t)r_in * 128u + (cByte ^ (((uint32_t)(r_in & 7) << 4) & 0x70u));
    *(uint2*)(g_ksw + (size_t)(nt * KSLABS + kslab) * B_SLAB + off) = pk;
}

// ------------------------- GEMM: f16 mma.sync, 256x256 tile, 16 warps -------------------------
__global__ __launch_bounds__(512, 1) void sim_gemm() {
    extern __shared__ __align__(16) unsigned char smraw[];   // NSTAGE * 64KB

    const int tid = threadIdx.x;
    const int lane = tid & 31, warp = tid >> 5;
    const int wr = warp >> 2;            // 4 warp-rows of 64
    const int wc = warp & 3;             // 4 warp-cols of 64
    const int wm = wr * 64;
    const int mt = blockIdx.x;
    const int nt = blockIdx.y;

    const unsigned char* qbase = g_qsw + (size_t)mt * KSLABS * A_SLAB;
    const unsigned char* kbase = g_ksw + (size_t)nt * KSLABS * B_SLAB;
    const uint32_t sbase = cvta_s(smraw);

    uint32_t acc[4][8][2];
    #pragma unroll
    for (int i = 0; i < 4; i++)
        #pragma unroll
        for (int j = 0; j < 8; j++) { acc[i][j][0] = 0u; acc[i][j][1] = 0u; }

    // prologue: slabs 0,1 into stages 0,1
    #pragma unroll
    for (int s = 0; s < NSTAGE - 1; ++s) {
        uint32_t st = sbase + s * STAGE_BYTES;
        #pragma unroll
        for (int i = 0; i < 4; ++i) {
            uint32_t o = (uint32_t)(i * 8192 + tid * 16);
            cp_async16(st + o,          qbase + (size_t)s * A_SLAB + o);
            cp_async16(st + A_SLAB + o, kbase + (size_t)s * B_SLAB + o);
        }
        cp_commit();
    }

    const uint32_t rsel = lane & 15;
    const uint32_t cbase = (uint32_t)((lane >> 4) << 4);   // 0 or 16 bytes

    #pragma unroll 1
    for (int t = 0; t < KSLABS; ++t) {
        cp_wait<NSTAGE - 2>();
        __syncthreads();
        if (t + NSTAGE - 1 < KSLABS) {
            int s2 = (t + NSTAGE - 1) % NSTAGE;
            uint32_t st = sbase + s2 * STAGE_BYTES;
            #pragma unroll
            for (int i = 0; i < 4; ++i) {
                uint32_t o = (uint32_t)(i * 8192 + tid * 16);
                cp_async16(st + o,          qbase + (size_t)(t + NSTAGE - 1) * A_SLAB + o);
                cp_async16(st + A_SLAB + o, kbase + (size_t)(t + NSTAGE - 1) * B_SLAB + o);
            }
        }
        cp_commit();

        uint32_t sA = sbase + (t % NSTAGE) * STAGE_BYTES;
        uint32_t sB = sA + A_SLAB;
        #pragma unroll
        for (int kk = 0; kk < 4; ++kk) {
            uint32_t cByte = (uint32_t)(kk * 32) + cbase;
            uint32_t af[4][4], bf[8][2];
            #pragma unroll
            for (int mi = 0; mi < 4; ++mi)
                ldsm4(af[mi][0], af[mi][1], af[mi][2], af[mi][3],
                      sA + swz(wm + mi * 16 + rsel, cByte));
            #pragma unroll
            for (int g = 0; g < 4; ++g) {
                uint32_t r0, r1, r2, r3;
                ldsm4(r0, r1, r2, r3, sB + swz(wc * 64 + g * 16 + rsel, cByte));
                bf[g*2+0][0] = r0; bf[g*2+0][1] = r2;
                bf[g*2+1][0] = r1; bf[g*2+1][1] = r3;
            }
            #pragma unroll
            for (int mi = 0; mi < 4; ++mi)
                #pragma unroll
                for (int ni = 0; ni < 8; ++ni)
                    mma_f16(acc[mi][ni], af[mi], bf[ni]);
        }
    }

    // register epilogue: per (row, 64-col warp tile) -> (max, runnerup|idx, sum, sumsq)
    const int rq = lane >> 2;            // row within 8
    const int lq = lane & 3;             // col quarter
    #pragma unroll
    for (int mi = 0; mi < 4; ++mi) {
        #pragma unroll
        for (int r = 0; r < 2; ++r) {
            float m1 = -1e30f, m2 = -1e30f; int i1 = 0;
            float s = 0.f, q = 0.f;
            #pragma unroll
            for (int ni = 0; ni < 8; ++ni) {
                float2 f = __half22float2(*(__half2*)&acc[mi][ni][r]);
                int c = ni * 8 + lq * 2;
                if (f.x > m1) { m2 = m1; m1 = f.x; i1 = c; } else m2 = fmaxf(m2, f.x);
                if (f.y > m1) { m2 = m1; m1 = f.y; i1 = c + 1; } else m2 = fmaxf(m2, f.y);
                s += f.x + f.y;
                q = fmaf(f.x, f.x, q); q = fmaf(f.y, f.y, q);
            }
            #pragma unroll
            for (int d = 1; d <= 2; d <<= 1) {
                float om1 = __shfl_xor_sync(0xffffffffu, m1, d, 4);
                float om2 = __shfl_xor_sync(0xffffffffu, m2, d, 4);
                int   oi  = __shfl_xor_sync(0xffffffffu, i1, d, 4);
                if (om1 > m1) { m2 = fmaxf(m1, om2); m1 = om1; i1 = oi; }
                else          { m2 = fmaxf(m2, om1); }
                s += __shfl_xor_sync(0xffffffffu, s, d, 4);
                q += __shfl_xor_sync(0xffffffffu, q, d, 4);
            }
            if (lq == 0) {
                int row = mt * BM + wm + mi * 16 + rq + r * 8;
                uint32_t pb = (__float_as_uint(m2) & ~63u) | (uint32_t)i1;
                g_blk[(size_t)row * NBLKS + nt * 4 + wc] =
                    make_float4(m1, __uint_as_float(pb), s, q);
            }
        }
    }
}

// ------------------------- finalize: warp per row, key-granular refinement -------------------------
__global__ __launch_bounds__(256) void finalize_rows(const float* __restrict__ keys,
                                                     const float* __restrict__ values,
                                                     float* __restrict__ out) {
    const int wid = threadIdx.x >> 5, lane = threadIdx.x & 31;
    const int row = blockIdx.x * 8 + wid;
    __shared__ int klist[8][16];
    __shared__ int blist[8][4];
    __shared__ int kcnt[8], bcnt[8];

    const float4* bp = (const float4*)g_blk + (size_t)row * NBLKS;
    float lm = -1e30f, s = 0.f, q2 = 0.f;
    #pragma unroll
    for (int i = 0; i < 16; ++i) {
        float4 b = bp[i * 32 + lane];
        lm = fmaxf(lm, b.x); s += b.z; q2 += b.w;
    }
    #pragma unroll
    for (int d = 16; d > 0; d >>= 1) {
        lm = fmaxf(lm, __shfl_xor_sync(0xffffffffu, lm, d));
        s  += __shfl_xor_sync(0xffffffffu, s,  d);
        q2 += __shfl_xor_sync(0xffffffffu, q2, d);
    }
    if (lane == 0) { kcnt[wid] = 0; bcnt[wid] = 0; }
    __syncwarp();
    float thr = lm - MARGIN;
    #pragma unroll
    for (int i = 0; i < 16; ++i) {
        float4 b = bp[i * 32 + lane];
        if (b.x >= thr) {
            int blk = i * 32 + lane;
            uint32_t pb = __float_as_uint(b.y);
            int p = atomicAdd(&kcnt[wid], 1);
            if (p < 16) klist[wid][p] = blk * 64 + (int)(pb & 63u);
            if (b.y >= thr) {             // runner-up near max -> refine whole block
                int p2 = atomicAdd(&bcnt[wid], 1);
                if (p2 < 4) blist[wid][p2] = blk;
            }
        }
    }
    __syncwarp();
    int nk = min(kcnt[wid], 16), nb = min(bcnt[wid], 4);

    float bv = -1e30f; int bi = 0x7fffffff;
    const float4* qp = (const float4*)(g_qn + (size_t)row * D_);
    for (int ci = 0; ci < nk; ++ci) {
        int n = klist[wid][ci];
        const float4* kp = (const float4*)(keys + (size_t)n * D_);
        float a0 = 0.f;
        #pragma unroll
        for (int j = 0; j < 8; ++j) {
            float4 qa = qp[j * 32 + lane], kb = kp[j * 32 + lane];
            a0 += qa.x*kb.x + qa.y*kb.y + qa.z*kb.z + qa.w*kb.w;
        }
        #pragma unroll
        for (int d = 16; d > 0; d >>= 1) a0 += __shfl_xor_sync(0xffffffffu, a0, d);
        float sv = a0 * g_kinv[n];
        if (sv > bv || (sv == bv && n < bi)) { bv = sv; bi = n; }
    }
    for (int ci = 0; ci < nb; ++ci) {
        int n0 = blist[wid][ci] * 64;
        #pragma unroll 1
        for (int kx = 0; kx < 64; ++kx) {
            int n = n0 + kx;
            const float4* kp = (const float4*)(keys + (size_t)n * D_);
            float a0 = 0.f;
            #pragma unroll
            for (int j = 0; j < 8; ++j) {
                float4 qa = qp[j * 32 + lane], kb = kp[j * 32 + lane];
                a0 += qa.x*kb.x + qa.y*kb.y + qa.z*kb.z + qa.w*kb.w;
            }
            #pragma unroll
            for (int d = 16; d > 0; d >>= 1) a0 += __shfl_xor_sync(0xffffffffu, a0, d);
            float sv = a0 * g_kinv[n];
            if (sv > bv || (sv == bv && n < bi)) { bv = sv; bi = n; }
        }
    }

    const float4* vp = (const float4*)(values + (size_t)bi * D_);
    float4* op = (float4*)(out + (size_t)row * D_);
    #pragma unroll
    for (int j = 0; j < 8; ++j) op[j * 32 + lane] = vp[j * 32 + lane];

    if (lane == 0)
        g_var[row] = (q2 - s * s * (1.0f / N_)) * (1.0f / (N_ - 1));
}

__global__ void var_mean(float* __restrict__ out, int out_size) {
    __shared__ float sh[256];
    int tid = threadIdx.x;
    float a = 0.f;
    for (int i = tid; i < B_; i += 256) a += g_var[i];
    sh[tid] = a; __syncthreads();
    for (int s = 128; s > 0; s >>= 1) { if (tid < s) sh[tid] += sh[tid + s]; __syncthreads(); }
    if (tid == 0) {
        long long base = (long long)B_ * D_;
        if (out_size > base) out[base] = sh[0] * (1.0f / B_);
    }
}

// ------------------------- launch -------------------------
extern "C" void kernel_launch(void* const* d_in, const int* in_sizes, int n_in,
                              void* d_out, int out_size) {
    const float* q = (const float*)d_in[0];
    const float* k = (const float*)d_in[1];
    const float* v = (const float*)d_in[2];
    float* out = (float*)d_out;

    const int dyn = NSTAGE * STAGE_BYTES;   // 196608
    cudaFuncSetAttribute(sim_gemm, cudaFuncAttributeMaxDynamicSharedMemorySize, dyn);

    norm_rows_q<<<B_, 256>>>(q);
    norm_rows_k<<<N_, 256>>>(k);
    dim3 g(B_ / BM, N_ / BN);     // m fastest -> K-tile reuse through L2
    sim_gemm<<<g, 512, dyn>>>();
    finalize_rows<<<B_ / 8, 256>>>(k, v, out);
    var_mean<<<1, 256>>>(out, out_size);
}